// round 5
// baseline (speedup 1.0000x reference)
#include <cuda_runtime.h>
#include <cstdint>

// Problem constants
#define B_   4
#define H_   384
#define W_   1280
#define GH_  192                 // int(0.5 * 384)
#define N_   (GH_ * W_)          // 245760 ground points per batch
#define HW_  (H_ * W_)           // 491520
#define HYP  25                  // MAX_IT
#define NPTS 5
#define TOLF 0.1f

#define NV_G (N_ / 4)            // 61440 float4 groups (ground region)
#define NV_A (HW_ / 4)           // 122880 float4 groups (full image)
#define NSAMP (B_ * HYP * NPTS)  // 500 sampled points

// Scratch (no cudaMalloc allowed)
__device__ float g_ws[B_ * HYP * 3];
__device__ int   g_cnt[B_ * HYP];

// ---------------------------------------------------------------------------
// Kernel 1: two-phase. Phase 1: 500 threads gather x/y/z for every sample
// (1500 independent LDGs in flight -> one DRAM latency round). Phase 2:
// threads 0..99 solve the 3x3 least-squares in fp64 from shared.
// A rows = [x, z, 1] (channels 0,2), Bm = y (channel 1 = vertical axis).
// M = A^T A + 1e-6 (scalar added to EVERY entry, matching jnp broadcast).
// ---------------------------------------------------------------------------
__global__ void __launch_bounds__(512) k_solve(const float* __restrict__ pts,
                                               const int* __restrict__ rind) {
    __shared__ float sx[NSAMP], sy[NSAMP], sz[NSAMP];
    int t = threadIdx.x;

    if (t < NSAMP) {
        int b = t / (HYP * NPTS);
        int r = t % (HYP * NPTS);
        int n = __ldg(rind + b * (HYP * NPTS) + r);
        const float* base = pts + (size_t)b * 3 * HW_ + (size_t)(H_ - GH_) * W_;
        float x = __ldg(base + n);
        float y = __ldg(base + HW_ + n);
        float z = __ldg(base + 2 * HW_ + n);
        sx[t] = x; sy[t] = y; sz[t] = z;
    }
    __syncthreads();

    if (t < B_ * HYP) {
        int o = t * NPTS;   // contiguous: (b,it) sample base

        double Sxx = 0, Sxz = 0, Sx = 0, Szz = 0, Sz = 0, Sxy = 0, Szy = 0, Sy = 0;
#pragma unroll
        for (int j = 0; j < NPTS; j++) {
            double x = (double)sx[o + j];
            double y = (double)sy[o + j];
            double z = (double)sz[o + j];
            Sxx += x * x; Sxz += x * z; Sx += x;
            Szz += z * z; Sz += z;
            Sxy += x * y; Szy += z * y; Sy += y;
        }

        const double e = 1e-6;
        double a  = Sxx + e, bb = Sxz + e, c = Sx + e;
        double d  = Szz + e, f  = Sz  + e;
        double g  = (double)NPTS + e;

        // Symmetric M = [[a,bb,c],[bb,d,f],[c,f,g]] — adjugate inverse
        double A00 = d * g - f * f;
        double A01 = c * f - bb * g;
        double A02 = bb * f - c * d;
        double det = a * A00 + bb * A01 + c * A02;
        double A11 = a * g - c * c;
        double A12 = bb * c - a * f;
        double A22 = a * d - bb * bb;
        double inv = 1.0 / det;

        double r0 = Sxy, r1 = Szy, r2 = Sy;
        g_ws[t * 3 + 0] = (float)((A00 * r0 + A01 * r1 + A02 * r2) * inv);
        g_ws[t * 3 + 1] = (float)((A01 * r0 + A11 * r1 + A12 * r2) * inv);
        g_ws[t * 3 + 2] = (float)((A02 * r0 + A12 * r1 + A22 * r2) * inv);
        g_cnt[t] = 0;
    }
}

// ---------------------------------------------------------------------------
// Kernel 2: inlier counting. Exact-cover grid: dim3(NV_G/256, B_), 256 thr,
// one float4 per thread (4 points x 25 hyps = 100 evals, fully ILP-exposed).
// Warp redux per hyp -> shared -> one global atomic per (block, hyp).
// ---------------------------------------------------------------------------
__global__ void __launch_bounds__(256) k_count(const float* __restrict__ pts) {
    int b = blockIdx.y;
    __shared__ float s_w[HYP * 3];
    __shared__ int   s_c[HYP];
    if (threadIdx.x < HYP * 3) s_w[threadIdx.x] = g_ws[b * HYP * 3 + threadIdx.x];
    if (threadIdx.x < HYP)     s_c[threadIdx.x] = 0;
    __syncthreads();

    const float4* xs = (const float4*)(pts + (size_t)b * 3 * HW_ + (size_t)(H_ - GH_) * W_);
    const float4* ys = xs + (HW_ / 4);
    const float4* zs = xs + 2 * (HW_ / 4);

    int v = blockIdx.x * blockDim.x + threadIdx.x;   // < NV_G by construction
    float4 X = xs[v];
    float4 Y = ys[v];
    float4 Z = zs[v];

#pragma unroll
    for (int k = 0; k < HYP; k++) {
        float w0 = s_w[3 * k], w1 = s_w[3 * k + 1], w2 = s_w[3 * k + 2];
        int c;
        c  = (fabsf(fmaf(X.x, w0, fmaf(Z.x, w1, w2)) - Y.x) < TOLF);
        c += (fabsf(fmaf(X.y, w0, fmaf(Z.y, w1, w2)) - Y.y) < TOLF);
        c += (fabsf(fmaf(X.z, w0, fmaf(Z.z, w1, w2)) - Y.z) < TOLF);
        c += (fabsf(fmaf(X.w, w0, fmaf(Z.w, w1, w2)) - Y.w) < TOLF);
        unsigned s = __reduce_add_sync(0xffffffffu, (unsigned)c);
        if ((threadIdx.x & 31) == 0) atomicAdd(&s_c[k], (int)s);
    }
    __syncthreads();
    if (threadIdx.x < HYP) atomicAdd(&g_cnt[b * HYP + threadIdx.x], s_c[threadIdx.x]);
}

// ---------------------------------------------------------------------------
// Kernel 3: fused pick + signed distance over ALL points (B,1,H,W).
// Every block redundantly computes the 25-way argmax (L2-resident, ~25 instrs;
// first-max tie rule matches jnp.argmax). Block (0,b) also writes best_w.
// Exact-cover grid: dim3(NV_A/256, B_), one float4 per thread, no loop.
// ---------------------------------------------------------------------------
__global__ void __launch_bounds__(256) k_dist(const float* __restrict__ pts,
                                              float* __restrict__ out,
                                              float* __restrict__ out_bw) {
    int b = blockIdx.y;

    int best = 0, bc = g_cnt[b * HYP];
#pragma unroll
    for (int it = 1; it < HYP; it++) {
        int v = g_cnt[b * HYP + it];
        if (v > bc) { bc = v; best = it; }
    }
    const float* wp = &g_ws[(b * HYP + best) * 3];
    float w0 = wp[0], w1 = wp[1], w2 = wp[2];

    if (blockIdx.x == 0 && threadIdx.x < 3) out_bw[b * 3 + threadIdx.x] = wp[threadIdx.x];

    const float4* xs = (const float4*)(pts + (size_t)b * 3 * HW_);
    const float4* ys = xs + (HW_ / 4);
    const float4* zs = xs + 2 * (HW_ / 4);
    float4* o = (float4*)(out + (size_t)b * HW_);

    int v = blockIdx.x * blockDim.x + threadIdx.x;   // < NV_A by construction
    float4 X = xs[v];
    float4 Y = ys[v];
    float4 Z = zs[v];
    float4 r;
    r.x = fmaf(X.x, w0, fmaf(Z.x, w1, w2)) - Y.x;
    r.y = fmaf(X.y, w0, fmaf(Z.y, w1, w2)) - Y.y;
    r.z = fmaf(X.z, w0, fmaf(Z.z, w1, w2)) - Y.z;
    r.w = fmaf(X.w, w0, fmaf(Z.w, w1, w2)) - Y.w;
    o[v] = r;
}

// ---------------------------------------------------------------------------
// Launch: 3 kernels, one stream, graph-capturable (no syncs, no allocs).
// Output layout: dist (B*H*W floats) followed by best_w (B*3 floats).
// ---------------------------------------------------------------------------
extern "C" void kernel_launch(void* const* d_in, const int* in_sizes, int n_in,
                              void* d_out, int out_size) {
    const float* pts  = (const float*)d_in[0];
    const int*   rind = (const int*)d_in[1];
    float*       out  = (float*)d_out;

    k_solve<<<1, 512>>>(pts, rind);
    k_count<<<dim3(NV_G / 256, B_), 256>>>(pts);
    k_dist<<<dim3(NV_A / 256, B_), 256>>>(pts, out, out + (size_t)B_ * HW_);
}

// round 8
// speedup vs baseline: 1.0102x; 1.0102x over previous
#include <cuda_runtime.h>
#include <cstdint>

// Problem constants
#define B_   4
#define H_   384
#define W_   1280
#define GH_  192                 // int(0.5 * 384)
#define N_   (GH_ * W_)          // 245760 ground points per batch
#define HW_  (H_ * W_)           // 491520
#define HYP  25                  // MAX_IT
#define NPTS 5
#define TOLF 0.1f

#define NV_G (N_ / 4)            // 61440 float4 groups (ground region)
#define NV_A (HW_ / 4)           // 122880 float4 groups (full image)
#define NSAMP (B_ * HYP * NPTS)  // 500 sampled points

// Scratch (no cudaMalloc allowed)
__device__ float g_ws[B_ * HYP * 3];
__device__ int   g_cnt[B_ * HYP];

// ---------------------------------------------------------------------------
// Kernel 1: gather 500 samples (1500 parallel LDGs), then 100 threads solve
// the 3x3 LS systems in fp64 with a SHORT critical path:
//   - pairwise-tree accumulation (depth 3 instead of 5)
//   - fp32-seeded Newton reciprocal instead of IEEE DDIV
// Triggers PDL completion at entry so k_count launches immediately.
// M = A^T A + 1e-6 added to EVERY entry (matches jnp broadcast).
// ---------------------------------------------------------------------------
__global__ void __launch_bounds__(512) k_solve(const float* __restrict__ pts,
                                               const int* __restrict__ rind) {
    cudaTriggerProgrammaticLaunchCompletion();

    __shared__ float sx[NSAMP], sy[NSAMP], sz[NSAMP];
    int t = threadIdx.x;

    if (t < NSAMP) {
        int b = t / (HYP * NPTS);
        int r = t % (HYP * NPTS);
        int n = __ldg(rind + b * (HYP * NPTS) + r);
        const float* base = pts + (size_t)b * 3 * HW_ + (size_t)(H_ - GH_) * W_;
        sx[t] = __ldg(base + n);
        sy[t] = __ldg(base + HW_ + n);
        sz[t] = __ldg(base + 2 * HW_ + n);
    }
    __syncthreads();

    if (t < B_ * HYP) {
        int o = t * NPTS;
        double x0 = sx[o], x1 = sx[o+1], x2 = sx[o+2], x3 = sx[o+3], x4 = sx[o+4];
        double y0 = sy[o], y1 = sy[o+1], y2 = sy[o+2], y3 = sy[o+3], y4 = sy[o+4];
        double z0 = sz[o], z1 = sz[o+1], z2 = sz[o+2], z3 = sz[o+3], z4 = sz[o+4];

        // Pairwise-tree sums: depth 3, 8 independent trees (ILP).
        #define PW(e0,e1,e2,e3,e4) (((e0)+(e1)) + (((e2)+(e3)) + (e4)))
        double Sxx = PW(x0*x0, x1*x1, x2*x2, x3*x3, x4*x4);
        double Sxz = PW(x0*z0, x1*z1, x2*z2, x3*z3, x4*z4);
        double Sx  = PW(x0, x1, x2, x3, x4);
        double Szz = PW(z0*z0, z1*z1, z2*z2, z3*z3, z4*z4);
        double Sz  = PW(z0, z1, z2, z3, z4);
        double Sxy = PW(x0*y0, x1*y1, x2*y2, x3*y3, x4*y4);
        double Szy = PW(z0*y0, z1*y1, z2*y2, z3*y3, z4*y4);
        double Sy  = PW(y0, y1, y2, y3, y4);
        #undef PW

        const double e = 1e-6;
        double a  = Sxx + e, bb = Sxz + e, c = Sx + e;
        double d  = Szz + e, f  = Sz  + e;
        double g  = (double)NPTS + e;

        // Symmetric M = [[a,bb,c],[bb,d,f],[c,f,g]] — adjugate (6 independent 2-deep terms)
        double A00 = d * g - f * f;
        double A01 = c * f - bb * g;
        double A02 = bb * f - c * d;
        double A11 = a * g - c * c;
        double A12 = bb * c - a * f;
        double A22 = a * d - bb * bb;
        double det = (a * A00 + bb * A01) + c * A02;

        // Reciprocal: fp32 seed + 2 fp64 Newton steps (~2^-46 rel err, output is fp32)
        double inv = (double)__frcp_rn((float)det);
        inv = inv * (2.0 - det * inv);
        inv = inv * (2.0 - det * inv);

        double r0 = Sxy, r1 = Szy, r2 = Sy;
        g_ws[t * 3 + 0] = (float)(((A00 * r0 + A01 * r1) + A02 * r2) * inv);
        g_ws[t * 3 + 1] = (float)(((A01 * r0 + A11 * r1) + A12 * r2) * inv);
        g_ws[t * 3 + 2] = (float)(((A02 * r0 + A12 * r1) + A22 * r2) * inv);
        g_cnt[t] = 0;
    }
}

// ---------------------------------------------------------------------------
// Kernel 2: inlier counting. PDL-dependent on k_solve: issue the three
// LDG.128s first (independent of solve), then grid-dependency-sync before
// reading g_ws. One float4/thread, exact-cover grid.
// ---------------------------------------------------------------------------
__global__ void __launch_bounds__(256) k_count(const float* __restrict__ pts) {
    int b = blockIdx.y;

    const float4* xs = (const float4*)(pts + (size_t)b * 3 * HW_ + (size_t)(H_ - GH_) * W_);
    const float4* ys = xs + (HW_ / 4);
    const float4* zs = xs + 2 * (HW_ / 4);

    int v = blockIdx.x * blockDim.x + threadIdx.x;   // < NV_G by construction
    float4 X = xs[v];
    float4 Y = ys[v];
    float4 Z = zs[v];

    __shared__ float s_w[HYP * 3];
    __shared__ int   s_c[HYP];

    cudaGridDependencySynchronize();   // k_solve's g_ws/g_cnt now visible

    if (threadIdx.x < HYP * 3) s_w[threadIdx.x] = g_ws[b * HYP * 3 + threadIdx.x];
    if (threadIdx.x < HYP)     s_c[threadIdx.x] = 0;
    __syncthreads();

    cudaTriggerProgrammaticLaunchCompletion();   // let k_dist start its loads

#pragma unroll
    for (int k = 0; k < HYP; k++) {
        float w0 = s_w[3 * k], w1 = s_w[3 * k + 1], w2 = s_w[3 * k + 2];
        int c;
        c  = (fabsf(fmaf(X.x, w0, fmaf(Z.x, w1, w2)) - Y.x) < TOLF);
        c += (fabsf(fmaf(X.y, w0, fmaf(Z.y, w1, w2)) - Y.y) < TOLF);
        c += (fabsf(fmaf(X.z, w0, fmaf(Z.z, w1, w2)) - Y.z) < TOLF);
        c += (fabsf(fmaf(X.w, w0, fmaf(Z.w, w1, w2)) - Y.w) < TOLF);
        unsigned s = __reduce_add_sync(0xffffffffu, (unsigned)c);
        if ((threadIdx.x & 31) == 0) atomicAdd(&s_c[k], (int)s);
    }
    __syncthreads();
    if (threadIdx.x < HYP) atomicAdd(&g_cnt[b * HYP + threadIdx.x], s_c[threadIdx.x]);
}

// ---------------------------------------------------------------------------
// Kernel 3: fused pick + signed distance. PDL-dependent on k_count: loads
// first, then sync, then the 25-way argmax (first-max tie rule = jnp.argmax).
// ---------------------------------------------------------------------------
__global__ void __launch_bounds__(256) k_dist(const float* __restrict__ pts,
                                              float* __restrict__ out,
                                              float* __restrict__ out_bw) {
    int b = blockIdx.y;

    const float4* xs = (const float4*)(pts + (size_t)b * 3 * HW_);
    const float4* ys = xs + (HW_ / 4);
    const float4* zs = xs + 2 * (HW_ / 4);
    float4* o = (float4*)(out + (size_t)b * HW_);

    int v = blockIdx.x * blockDim.x + threadIdx.x;   // < NV_A by construction
    float4 X = xs[v];
    float4 Y = ys[v];
    float4 Z = zs[v];

    cudaGridDependencySynchronize();   // k_count's g_cnt now visible

    int best = 0, bc = g_cnt[b * HYP];
#pragma unroll
    for (int it = 1; it < HYP; it++) {
        int c = g_cnt[b * HYP + it];
        if (c > bc) { bc = c; best = it; }
    }
    const float* wp = &g_ws[(b * HYP + best) * 3];
    float w0 = wp[0], w1 = wp[1], w2 = wp[2];

    if (blockIdx.x == 0 && threadIdx.x < 3) out_bw[b * 3 + threadIdx.x] = wp[threadIdx.x];

    float4 r;
    r.x = fmaf(X.x, w0, fmaf(Z.x, w1, w2)) - Y.x;
    r.y = fmaf(X.y, w0, fmaf(Z.y, w1, w2)) - Y.y;
    r.z = fmaf(X.z, w0, fmaf(Z.z, w1, w2)) - Y.z;
    r.w = fmaf(X.w, w0, fmaf(Z.w, w1, w2)) - Y.w;
    o[v] = r;
}

// ---------------------------------------------------------------------------
// Launch: 3 kernels chained with Programmatic Dependent Launch so each
// successor overlaps its predecessor's tail. Graph-capturable (PDL edges are
// supported in stream capture); no syncs, no allocs.
// Output layout: dist (B*H*W floats) followed by best_w (B*3 floats).
// ---------------------------------------------------------------------------
extern "C" void kernel_launch(void* const* d_in, const int* in_sizes, int n_in,
                              void* d_out, int out_size) {
    const float* pts  = (const float*)d_in[0];
    const int*   rind = (const int*)d_in[1];
    float*       out  = (float*)d_out;

    k_solve<<<1, 512>>>(pts, rind);

    cudaLaunchAttribute pdl[1];
    pdl[0].id = cudaLaunchAttributeProgrammaticStreamSerialization;
    pdl[0].val.programmaticStreamSerializationAllowed = 1;

    {
        cudaLaunchConfig_t cfg = {};
        cfg.gridDim  = dim3(NV_G / 256, B_);
        cfg.blockDim = dim3(256);
        cfg.attrs = pdl;
        cfg.numAttrs = 1;
        cudaLaunchKernelEx(&cfg, k_count, pts);
    }
    {
        cudaLaunchConfig_t cfg = {};
        cfg.gridDim  = dim3(NV_A / 256, B_);
        cfg.blockDim = dim3(256);
        cfg.attrs = pdl;
        cfg.numAttrs = 1;
        cudaLaunchKernelEx(&cfg, k_dist, pts, out, out + (size_t)B_ * HW_);
    }
}

// round 9
// speedup vs baseline: 1.0894x; 1.0784x over previous
#include <cuda_runtime.h>
#include <cstdint>

// Problem constants
#define B_   4
#define H_   384
#define W_   1280
#define GH_  192                 // int(0.5 * 384)
#define N_   (GH_ * W_)          // 245760 ground points per batch
#define HW_  (H_ * W_)           // 491520
#define HYP  25                  // MAX_IT
#define NPTS 5
#define TOLF 0.1f

#define NV_G (N_ / 4)            // 61440 float4 groups per batch (ground)
#define NV_A (HW_ / 4)           // 122880 float4 groups per batch (full)

// Kernel A geometry: grid (80, 4) x 256 threads, 3 float4/thread -> exact cover
#define GA_X 80
#define FPT_A 3
// Kernel B geometry: grid (160, 4) x 256 threads, 3 float4/thread -> exact cover
#define GB_X 160
#define FPT_B 3

// Scratch (no cudaMalloc allowed). Zero-initialized at load; kernel A's ticket
// logic restores them to zero at the end of every run (deterministic replays).
__device__ int          g_cnt[B_ * HYP];
__device__ unsigned int g_done[B_];
__device__ float        g_best[B_ * 3];

// ---------------------------------------------------------------------------
// Kernel A: fused solve + count + argmax.
//  - prefetch this thread's 3 count float4s (overlaps everything below)
//  - gather the batch's 125 samples (L2-hot after first blocks)
//  - threads 0..24 redundantly solve the 25 LS systems (fp64, short chain,
//    Newton reciprocal) -> smem. Redundant chip-wide cost ~ negligible.
//  - PDL trigger so k_dist can start streaming its loads
//  - count inliers (12 points x 25 hyps per thread), warp redux -> smem ->
//    one global atomic per (block, hyp)
//  - ticket: last block per batch computes argmax (first-max = jnp.argmax),
//    writes g_best, and RESETS g_cnt/g_done for the next graph replay.
// M = A^T A + 1e-6 added to EVERY entry (matches jnp broadcast).
// ---------------------------------------------------------------------------
__global__ void __launch_bounds__(256) k_fit(const float* __restrict__ pts,
                                             const int* __restrict__ rind) {
    const int b   = blockIdx.y;
    const int tid = threadIdx.x;

    const float4* xs = (const float4*)(pts + (size_t)b * 3 * HW_ + (size_t)(H_ - GH_) * W_);
    const float4* ys = xs + (HW_ / 4);
    const float4* zs = xs + 2 * (HW_ / 4);

    // Prefetch count data (9 independent LDG.128, in flight during solve)
    const int v0 = blockIdx.x * (256 * FPT_A) + tid;
    float4 X[FPT_A], Y[FPT_A], Z[FPT_A];
#pragma unroll
    for (int i = 0; i < FPT_A; i++) {
        X[i] = xs[v0 + i * 256];
        Y[i] = ys[v0 + i * 256];
        Z[i] = zs[v0 + i * 256];
    }

    __shared__ float sx[HYP * NPTS], sy[HYP * NPTS], sz[HYP * NPTS];
    __shared__ float s_w[HYP * 3];
    __shared__ int   s_c[HYP];

    // Gather this batch's 125 samples
    if (tid < HYP * NPTS) {
        int n = __ldg(rind + b * (HYP * NPTS) + tid);
        const float* base = pts + (size_t)b * 3 * HW_ + (size_t)(H_ - GH_) * W_;
        sx[tid] = __ldg(base + n);
        sy[tid] = __ldg(base + HW_ + n);
        sz[tid] = __ldg(base + 2 * HW_ + n);
    }
    if (tid < HYP) s_c[tid] = 0;
    __syncthreads();

    // Solve (threads 0..24, one hypothesis each)
    if (tid < HYP) {
        int o = tid * NPTS;
        double x0 = sx[o], x1 = sx[o+1], x2 = sx[o+2], x3 = sx[o+3], x4 = sx[o+4];
        double y0 = sy[o], y1 = sy[o+1], y2 = sy[o+2], y3 = sy[o+3], y4 = sy[o+4];
        double z0 = sz[o], z1 = sz[o+1], z2 = sz[o+2], z3 = sz[o+3], z4 = sz[o+4];

        #define PW(e0,e1,e2,e3,e4) (((e0)+(e1)) + (((e2)+(e3)) + (e4)))
        double Sxx = PW(x0*x0, x1*x1, x2*x2, x3*x3, x4*x4);
        double Sxz = PW(x0*z0, x1*z1, x2*z2, x3*z3, x4*z4);
        double Sx  = PW(x0, x1, x2, x3, x4);
        double Szz = PW(z0*z0, z1*z1, z2*z2, z3*z3, z4*z4);
        double Sz  = PW(z0, z1, z2, z3, z4);
        double Sxy = PW(x0*y0, x1*y1, x2*y2, x3*y3, x4*y4);
        double Szy = PW(z0*y0, z1*y1, z2*y2, z3*y3, z4*y4);
        double Sy  = PW(y0, y1, y2, y3, y4);
        #undef PW

        const double e = 1e-6;
        double a  = Sxx + e, bb = Sxz + e, c = Sx + e;
        double d  = Szz + e, f  = Sz  + e;
        double g  = (double)NPTS + e;

        double A00 = d * g - f * f;
        double A01 = c * f - bb * g;
        double A02 = bb * f - c * d;
        double A11 = a * g - c * c;
        double A12 = bb * c - a * f;
        double A22 = a * d - bb * bb;
        double det = (a * A00 + bb * A01) + c * A02;

        // fp32-seeded Newton reciprocal (~2^-46 rel err; outputs are fp32)
        double inv = (double)__frcp_rn((float)det);
        inv = inv * (2.0 - det * inv);
        inv = inv * (2.0 - det * inv);

        double r0 = Sxy, r1 = Szy, r2 = Sy;
        s_w[tid * 3 + 0] = (float)(((A00 * r0 + A01 * r1) + A02 * r2) * inv);
        s_w[tid * 3 + 1] = (float)(((A01 * r0 + A11 * r1) + A12 * r2) * inv);
        s_w[tid * 3 + 2] = (float)(((A02 * r0 + A12 * r1) + A22 * r2) * inv);
    }
    __syncthreads();

    // Let k_dist launch and start streaming its loads while we count
    cudaTriggerProgrammaticLaunchCompletion();

    // Count: 12 points x 25 hypotheses per thread
    for (int k = 0; k < HYP; k++) {
        float w0 = s_w[3 * k], w1 = s_w[3 * k + 1], w2 = s_w[3 * k + 2];
        int c = 0;
#pragma unroll
        for (int i = 0; i < FPT_A; i++) {
            c += (fabsf(fmaf(X[i].x, w0, fmaf(Z[i].x, w1, w2)) - Y[i].x) < TOLF);
            c += (fabsf(fmaf(X[i].y, w0, fmaf(Z[i].y, w1, w2)) - Y[i].y) < TOLF);
            c += (fabsf(fmaf(X[i].z, w0, fmaf(Z[i].z, w1, w2)) - Y[i].z) < TOLF);
            c += (fabsf(fmaf(X[i].w, w0, fmaf(Z[i].w, w1, w2)) - Y[i].w) < TOLF);
        }
        unsigned s = __reduce_add_sync(0xffffffffu, (unsigned)c);
        if ((tid & 31) == 0) atomicAdd(&s_c[k], (int)s);
    }
    __syncthreads();
    if (tid < HYP) atomicAdd(&g_cnt[b * HYP + tid], s_c[tid]);
    __syncthreads();

    // Ticket: last block of this batch does argmax + reset (race-free,
    // self-resetting -> deterministic across graph replays)
    if (tid == 0) {
        __threadfence();
        unsigned old = atomicAdd(&g_done[b], 1u);
        if (old == GA_X - 1) {
            __threadfence();
            int best = 0, bc = __ldcg(&g_cnt[b * HYP]);
#pragma unroll
            for (int it = 1; it < HYP; it++) {
                int v = __ldcg(&g_cnt[b * HYP + it]);
                if (v > bc) { bc = v; best = it; }
            }
            g_best[b * 3 + 0] = s_w[best * 3 + 0];
            g_best[b * 3 + 1] = s_w[best * 3 + 1];
            g_best[b * 3 + 2] = s_w[best * 3 + 2];
            // reset for next replay
#pragma unroll
            for (int it = 0; it < HYP; it++) g_cnt[b * HYP + it] = 0;
            g_done[b] = 0;
            __threadfence();
        }
    }
}

// ---------------------------------------------------------------------------
// Kernel B: signed distance over ALL points + best_w output.
// PDL-dependent: issue all 9 LDG.128 first (overlaps k_fit's count phase),
// then grid-dependency-sync, then read g_best.
// ---------------------------------------------------------------------------
__global__ void __launch_bounds__(256) k_dist(const float* __restrict__ pts,
                                              float* __restrict__ out,
                                              float* __restrict__ out_bw) {
    const int b   = blockIdx.y;
    const int tid = threadIdx.x;

    const float4* xs = (const float4*)(pts + (size_t)b * 3 * HW_);
    const float4* ys = xs + (HW_ / 4);
    const float4* zs = xs + 2 * (HW_ / 4);
    float4* o = (float4*)(out + (size_t)b * HW_);

    const int v0 = blockIdx.x * (256 * FPT_B) + tid;
    float4 X[FPT_B], Y[FPT_B], Z[FPT_B];
#pragma unroll
    for (int i = 0; i < FPT_B; i++) {
        X[i] = xs[v0 + i * 256];
        Y[i] = ys[v0 + i * 256];
        Z[i] = zs[v0 + i * 256];
    }

    cudaGridDependencySynchronize();   // k_fit's g_best now visible

    float w0 = g_best[b * 3 + 0];
    float w1 = g_best[b * 3 + 1];
    float w2 = g_best[b * 3 + 2];

    if (blockIdx.x == 0 && tid < 3) out_bw[b * 3 + tid] = g_best[b * 3 + tid];

#pragma unroll
    for (int i = 0; i < FPT_B; i++) {
        float4 r;
        r.x = fmaf(X[i].x, w0, fmaf(Z[i].x, w1, w2)) - Y[i].x;
        r.y = fmaf(X[i].y, w0, fmaf(Z[i].y, w1, w2)) - Y[i].y;
        r.z = fmaf(X[i].z, w0, fmaf(Z[i].z, w1, w2)) - Y[i].z;
        r.w = fmaf(X[i].w, w0, fmaf(Z[i].w, w1, w2)) - Y[i].w;
        o[v0 + i * 256] = r;
    }
}

// ---------------------------------------------------------------------------
// Launch: 2 kernels, PDL-chained, graph-capturable (no syncs, no allocs).
// Output layout: dist (B*H*W floats) followed by best_w (B*3 floats).
// ---------------------------------------------------------------------------
extern "C" void kernel_launch(void* const* d_in, const int* in_sizes, int n_in,
                              void* d_out, int out_size) {
    const float* pts  = (const float*)d_in[0];
    const int*   rind = (const int*)d_in[1];
    float*       out  = (float*)d_out;

    k_fit<<<dim3(GA_X, B_), 256>>>(pts, rind);

    cudaLaunchAttribute pdl[1];
    pdl[0].id = cudaLaunchAttributeProgrammaticStreamSerialization;
    pdl[0].val.programmaticStreamSerializationAllowed = 1;

    cudaLaunchConfig_t cfg = {};
    cfg.gridDim  = dim3(GB_X, B_);
    cfg.blockDim = dim3(256);
    cfg.attrs = pdl;
    cfg.numAttrs = 1;
    cudaLaunchKernelEx(&cfg, k_dist, pts, out, out + (size_t)B_ * HW_);
}